// round 10
// baseline (speedup 1.0000x reference)
#include <cuda_runtime.h>
#include <cuda_bf16.h>
#include <cfloat>
#include <cstdint>
#include <cstddef>

#define MARGINF 0.3f
#define BIGF    9999999.0f
#define MAXN    8192
#define NSPLIT  4
#define SKP     40      // padded smem row stride in elements (80B, conflict-free, 16B-mult)

// ---------------- scratch (device globals; no allocation allowed) ----------------
__device__ __align__(16) __nv_bfloat16 g_hi[(size_t)MAXN * 1024];
__device__ __align__(16) __nv_bfloat16 g_lo[(size_t)MAXN * 1024];
__device__ float g_sq[MAXN];
__device__ float g_nrm[MAXN];
__device__ int   g_lab[MAXN];
__device__ float g_pv1[NSPLIT * MAXN];
__device__ float g_pv2[NSPLIT * MAXN];
__device__ int   g_pi1[NSPLIT * MAXN];
__device__ int   g_pi2[NSPLIT * MAXN];
__device__ float g_pan[NSPLIT * MAXN];
__device__ float g_ap1[MAXN];
__device__ float g_ap2[MAXN];
__device__ int   g_i1[MAXN];
__device__ int   g_i2[MAXN];
__device__ float g_an[MAXN];
__device__ float g_l11[MAXN];
__device__ float g_l13[MAXN];
__device__ float g_pr[MAXN];
__device__ int   g_lab64;
__device__ int   g_bad;

// ---------------- small asm helpers (all baseline sm_80+ features) ----------------
__device__ __forceinline__ uint32_t smem_u32(const void* p) {
    uint32_t a;
    asm("{ .reg .u64 t; cvta.to.shared.u64 t, %1; cvt.u32.u64 %0, t; }" : "=r"(a) : "l"(p));
    return a;
}
__device__ __forceinline__ void cp16(uint32_t s, const void* g) {
    asm volatile("cp.async.cg.shared.global [%0], [%1], 16;" :: "r"(s), "l"(g));
}
__device__ __forceinline__ void ldsm_x4(uint32_t& r0, uint32_t& r1, uint32_t& r2, uint32_t& r3, uint32_t a) {
    asm volatile("ldmatrix.sync.aligned.m8n8.x4.shared.b16 {%0,%1,%2,%3}, [%4];"
        : "=r"(r0), "=r"(r1), "=r"(r2), "=r"(r3) : "r"(a));
}
__device__ __forceinline__ void ldsm_x2(uint32_t& r0, uint32_t& r1, uint32_t a) {
    asm volatile("ldmatrix.sync.aligned.m8n8.x2.shared.b16 {%0,%1}, [%2];"
        : "=r"(r0), "=r"(r1) : "r"(a));
}
__device__ __forceinline__ void mma16816(float* c, uint32_t a0, uint32_t a1,
                                         uint32_t a2, uint32_t a3,
                                         uint32_t b0, uint32_t b1) {
    asm volatile(
        "mma.sync.aligned.m16n8k16.row.col.f32.bf16.bf16.f32 "
        "{%0,%1,%2,%3}, {%4,%5,%6,%7}, {%8,%9}, {%0,%1,%2,%3};"
        : "+f"(c[0]), "+f"(c[1]), "+f"(c[2]), "+f"(c[3])
        : "r"(a0), "r"(a1), "r"(a2), "r"(a3), "r"(b0), "r"(b1));
}

// ---------------- label dtype detection + flag reset ----------------
__global__ void detect_label_kernel(const int* lab_raw) {
    if (threadIdx.x == 0 && blockIdx.x == 0) {
        int nz = 0;
        for (int i = 0; i < 64; i++) nz |= lab_raw[2 * i + 1];
        g_lab64 = (nz == 0) ? 1 : 0;
        g_bad = 0;
    }
}

// ---------------- per-row precompute: sq, nrm, label32 ----------------
__global__ void precompute_kernel(const float* __restrict__ emb,
                                  const float* __restrict__ clot,
                                  const void* __restrict__ label,
                                  int D, int D2) {
    int row = blockIdx.x;
    const float* e = emb + (size_t)row * D;
    const float* c = clot + (size_t)row * D2;
    float s = 0.f, s2 = 0.f;
    for (int t = threadIdx.x; t < D; t += blockDim.x) { float v = e[t]; s += v * v; }
    for (int t = threadIdx.x; t < D2; t += blockDim.x) { float v = c[t]; s2 += v * v; }
    #pragma unroll
    for (int o = 16; o > 0; o >>= 1) {
        s  += __shfl_down_sync(0xffffffffu, s,  o);
        s2 += __shfl_down_sync(0xffffffffu, s2, o);
    }
    __shared__ float red[2][8];
    int w = threadIdx.x >> 5, l = threadIdx.x & 31;
    if (l == 0) { red[0][w] = s; red[1][w] = s2; }
    __syncthreads();
    if (threadIdx.x == 0) {
        float a = 0.f, b = 0.f;
        int nw = blockDim.x >> 5;
        for (int i = 0; i < nw; i++) { a += red[0][i]; b += red[1][i]; }
        g_sq[row]  = a;
        g_nrm[row] = sqrtf(b);
        if (g_lab64) g_lab[row] = (int)((const long long*)label)[row];
        else         g_lab[row] = ((const int*)label)[row];
    }
}

// ---------------- convert fp32 -> bf16 hi/lo (row-major) ----------------
__global__ void convert_kernel(const float* __restrict__ emb, int N, int D) {
    int row = blockIdx.x;
    for (int k8 = threadIdx.x * 8; k8 < D; k8 += blockDim.x * 8) {
        float4 x0 = *reinterpret_cast<const float4*>(emb + (size_t)row * D + k8);
        float4 x1 = *reinterpret_cast<const float4*>(emb + (size_t)row * D + k8 + 4);
        float xs[8] = {x0.x, x0.y, x0.z, x0.w, x1.x, x1.y, x1.z, x1.w};
        unsigned short hs[8], ls[8];
        #pragma unroll
        for (int e = 0; e < 8; e++) {
            __nv_bfloat16 h = __float2bfloat16(xs[e]);
            float r = xs[e] - __bfloat162float(h);
            __nv_bfloat16 l = __float2bfloat16(r);
            hs[e] = __bfloat16_as_ushort(h);
            ls[e] = __bfloat16_as_ushort(l);
        }
        uint4 hp, lp;
        hp.x = ((uint32_t)hs[1] << 16) | hs[0]; hp.y = ((uint32_t)hs[3] << 16) | hs[2];
        hp.z = ((uint32_t)hs[5] << 16) | hs[4]; hp.w = ((uint32_t)hs[7] << 16) | hs[6];
        lp.x = ((uint32_t)ls[1] << 16) | ls[0]; lp.y = ((uint32_t)ls[3] << 16) | ls[2];
        lp.z = ((uint32_t)ls[5] << 16) | ls[4]; lp.w = ((uint32_t)ls[7] << 16) | ls[6];
        *reinterpret_cast<uint4*>(g_hi + (size_t)row * D + k8) = hp;
        *reinterpret_cast<uint4*>(g_lo + (size_t)row * D + k8) = lp;
    }
}

// ---------------- fused bf16 mma.sync GEMM (3-pass hi/lo) + row reductions ----------------
// BM=BN=128, BK=32, 512 threads = 16 warps in 4(m) x 4(n) grid; each warp 2x4 m16n8k16 tiles.
__global__ __launch_bounds__(512, 1)
void dist_hmma_kernel(int N, int D) {
    __shared__ __align__(16) char smraw[43008];
    // tiles: As [2][128][SKP], Bs [2][128][SKP] bf16 (20480B each); sqc/labc after.
    uint32_t as0 = smem_u32(smraw);
    uint32_t bs0 = as0 + 20480;
    float* sqc  = (float*)(smraw + 40960);
    int*   labc = (int*)(smraw + 41472);

    const int tid  = threadIdx.x;
    const int lane = tid & 31;
    const int wid  = tid >> 5;
    const int wm   = wid >> 2;        // 0..3
    const int wn   = wid & 3;         // 0..3
    const int g    = lane >> 2;       // 0..7
    const int q    = lane & 3;        // 0..3
    const int i0   = blockIdx.x * 128;
    const int jw   = N / NSPLIT;
    const int jlo  = blockIdx.y * jw;
    const int nk   = D / 32;
    const int NS   = 3 * nk;          // stages per j-tile (3 passes)

    // ldmatrix lane-address components
    const int ar = (lane & 7) + ((lane >> 3) & 1) * 8;  // A: row within m16
    const int ak = (lane >> 4) * 8;                     // A: k-offset
    const int bl = lane & 7;                            // B: row within n8
    const int bk = ((lane >> 3) & 1) * 8;               // B: k-offset

    // per-thread row constants (4 rows owned: 2 mi-tiles x {g, g+8})
    float sqr4[4]; int labr4[4];
    #pragma unroll
    for (int mi = 0; mi < 2; mi++)
        #pragma unroll
        for (int rr = 0; rr < 2; rr++) {
            int r = i0 + wm * 32 + mi * 16 + rr * 8 + g;
            sqr4[mi * 2 + rr]  = g_sq[r];
            labr4[mi * 2 + rr] = g_lab[r];
        }

    float v1[4], v2[4], an[4]; int ix1[4], ix2[4];
    #pragma unroll
    for (int s = 0; s < 4; s++) {
        v1[s] = -FLT_MAX; v2[s] = -FLT_MAX; an[s] = FLT_MAX; ix1[s] = 0; ix2[s] = 0;
    }

    const int crow = tid >> 2, cchk = tid & 3;   // cp.async mapping: 128 rows x 4 16B chunks

    for (int jt = 0; jt < jw / 128; jt++) {
        const int j0 = jlo + jt * 128;
        __syncthreads();
        if (tid < 128) { sqc[tid] = g_sq[j0 + tid]; labc[tid] = g_lab[j0 + tid]; }

        float acc[2][4][4];
        #pragma unroll
        for (int mi = 0; mi < 2; mi++)
            #pragma unroll
            for (int ni = 0; ni < 4; ni++)
                #pragma unroll
                for (int e = 0; e < 4; e++) acc[mi][ni][e] = 0.f;

        // prologue: stage 0 -> buf 0 (pass 0: hi*hi, kc 0)
        {
            const __nv_bfloat16* gA = g_hi + (size_t)(i0 + crow) * D + cchk * 8;
            const __nv_bfloat16* gB = g_hi + (size_t)(j0 + crow) * D + cchk * 8;
            cp16(as0 + (crow * SKP + cchk * 8) * 2, gA);
            cp16(bs0 + (crow * SKP + cchk * 8) * 2, gB);
            asm volatile("cp.async.commit_group;");
        }

        for (int s = 0; s < NS; s++) {
            if (s + 1 < NS) {
                int sp = s + 1;
                int p = sp / nk, kc = sp % nk;
                const __nv_bfloat16* Asrc = (p == 2) ? g_lo : g_hi;
                const __nv_bfloat16* Bsrc = (p == 1) ? g_lo : g_hi;
                const __nv_bfloat16* gA = Asrc + (size_t)(i0 + crow) * D + kc * 32 + cchk * 8;
                const __nv_bfloat16* gB = Bsrc + (size_t)(j0 + crow) * D + kc * 32 + cchk * 8;
                uint32_t buf = (uint32_t)(sp & 1) * 10240u;
                cp16(as0 + buf + (crow * SKP + cchk * 8) * 2, gA);
                cp16(bs0 + buf + (crow * SKP + cchk * 8) * 2, gB);
                asm volatile("cp.async.commit_group;");
                asm volatile("cp.async.wait_group 1;");
            } else {
                asm volatile("cp.async.wait_group 0;");
            }
            __syncthreads();

            // compute buf s&1
            uint32_t ab = as0 + (uint32_t)(s & 1) * 10240u;
            uint32_t bb = bs0 + (uint32_t)(s & 1) * 10240u;
            #pragma unroll
            for (int kk = 0; kk < 32; kk += 16) {
                uint32_t bfr[4][2];
                #pragma unroll
                for (int ni = 0; ni < 4; ni++) {
                    uint32_t baddr = bb + (((wn * 32 + ni * 8 + bl) * SKP) + kk + bk) * 2;
                    ldsm_x2(bfr[ni][0], bfr[ni][1], baddr);
                }
                #pragma unroll
                for (int mi = 0; mi < 2; mi++) {
                    uint32_t aaddr = ab + (((wm * 32 + mi * 16 + ar) * SKP) + kk + ak) * 2;
                    uint32_t a0, a1, a2, a3;
                    ldsm_x4(a0, a1, a2, a3, aaddr);
                    #pragma unroll
                    for (int ni = 0; ni < 4; ni++)
                        mma16816(acc[mi][ni], a0, a1, a2, a3, bfr[ni][0], bfr[ni][1]);
                }
            }
            __syncthreads();
        }

        // ---- tile epilogue: masked top2/min updates in d^2 domain ----
        #pragma unroll
        for (int mi = 0; mi < 2; mi++)
            #pragma unroll
            for (int rr = 0; rr < 2; rr++) {
                int st = mi * 2 + rr;
                #pragma unroll
                for (int ni = 0; ni < 4; ni++)
                    #pragma unroll
                    for (int e = 0; e < 2; e++) {
                        int col = wn * 32 + ni * 8 + q * 2 + e;
                        float dot = acc[mi][ni][rr * 2 + e];
                        float d2v = fmaf(-2.f, dot, sqr4[st] + sqc[col]);
                        d2v = fmaxf(d2v, 1e-12f);
                        bool same = (labr4[st] == labc[col]);
                        float v = same ? d2v : d2v - BIGF;
                        float w = same ? d2v + BIGF : d2v;
                        if (w < an[st]) an[st] = w;
                        int jg = j0 + col;
                        if (v > v1[st])      { v2[st] = v1[st]; ix2[st] = ix1[st]; v1[st] = v; ix1[st] = jg; }
                        else if (v > v2[st]) { v2[st] = v; ix2[st] = jg; }
                    }
            }
    }

    // ---- cross-thread merge: 16 partials per row via smem (alias tile memory) ----
    __syncthreads();
    float* Sv1 = (float*)smraw;               // [128][16]
    float* Sv2 = (float*)(smraw + 8192);
    float* San = (float*)(smraw + 16384);
    int*   Si1 = (int*)(smraw + 24576);
    int*   Si2 = (int*)(smraw + 32768);
    int slot = wn * 4 + q;
    #pragma unroll
    for (int mi = 0; mi < 2; mi++)
        #pragma unroll
        for (int rr = 0; rr < 2; rr++) {
            int st = mi * 2 + rr;
            int rowL = wm * 32 + mi * 16 + rr * 8 + g;
            Sv1[rowL * 16 + slot] = v1[st]; Si1[rowL * 16 + slot] = ix1[st];
            Sv2[rowL * 16 + slot] = v2[st]; Si2[rowL * 16 + slot] = ix2[st];
            San[rowL * 16 + slot] = an[st];
        }
    __syncthreads();
    if (tid < 128) {
        int r = tid;
        float bv1 = -FLT_MAX, bv2 = -FLT_MAX, ban = FLT_MAX;
        int bi1 = 0, bi2 = 0;
        #pragma unroll 4
        for (int t = 0; t < 16; t++) {
            float a = San[r * 16 + t];
            if (a < ban) ban = a;
            float cv = Sv1[r * 16 + t]; int ci = Si1[r * 16 + t];
            if (cv > bv1 || (cv == bv1 && ci < bi1)) { bv2 = bv1; bi2 = bi1; bv1 = cv; bi1 = ci; }
            else if (cv > bv2 || (cv == bv2 && ci < bi2)) { bv2 = cv; bi2 = ci; }
            cv = Sv2[r * 16 + t]; ci = Si2[r * 16 + t];
            if (cv > bv1 || (cv == bv1 && ci < bi1)) { bv2 = bv1; bi2 = bi1; bv1 = cv; bi1 = ci; }
            else if (cv > bv2 || (cv == bv2 && ci < bi2)) { bv2 = cv; bi2 = ci; }
        }
        // d^2 -> d domain (undo BIG masking, sqrt, re-apply)
        float ap1 = (bv1 > -BIGF * 0.5f) ? sqrtf(bv1) : (sqrtf(fmaxf(bv1 + BIGF, 1e-12f)) - BIGF);
        float ap2 = (bv2 > -BIGF * 0.5f) ? sqrtf(bv2) : (sqrtf(fmaxf(bv2 + BIGF, 1e-12f)) - BIGF);
        float anv = (ban <  BIGF * 0.5f) ? sqrtf(ban) : (sqrtf(fmaxf(ban - BIGF, 1e-12f)) + BIGF);
        int ig = i0 + r;
        int sidx = blockIdx.y;
        g_pv1[sidx * MAXN + ig] = ap1; g_pv2[sidx * MAXN + ig] = ap2;
        g_pi1[sidx * MAXN + ig] = bi1; g_pi2[sidx * MAXN + ig] = bi2;
        g_pan[sidx * MAXN + ig] = anv;
    }
}

// ---------------- merge column splits (deterministic) ----------------
__global__ void merge_split_kernel(int N) {
    int r = blockIdx.x * blockDim.x + threadIdx.x;
    if (r >= N) return;
    float bv1 = -FLT_MAX, bv2 = -FLT_MAX, ban = FLT_MAX;
    int bi1 = 0, bi2 = 0;
    #pragma unroll
    for (int s = 0; s < NSPLIT; s++) {
        float a = g_pan[s * MAXN + r];
        if (a < ban) ban = a;
        float cv = g_pv1[s * MAXN + r]; int ci = g_pi1[s * MAXN + r];
        if (cv > bv1 || (cv == bv1 && ci < bi1)) { bv2 = bv1; bi2 = bi1; bv1 = cv; bi1 = ci; }
        else if (cv > bv2 || (cv == bv2 && ci < bi2)) { bv2 = cv; bi2 = ci; }
        cv = g_pv2[s * MAXN + r]; ci = g_pi2[s * MAXN + r];
        if (cv > bv1 || (cv == bv1 && ci < bi1)) { bv2 = bv1; bi2 = bi1; bv1 = cv; bi1 = ci; }
        else if (cv > bv2 || (cv == bv2 && ci < bi2)) { bv2 = cv; bi2 = ci; }
    }
    g_ap1[r] = bv1; g_ap2[r] = bv2;
    g_i1[r] = bi1;  g_i2[r] = bi2;
    g_an[r] = ban;
}

// ---------------- validate vs exact fp32 at selected indices ----------------
__global__ void validate_kernel(const float* __restrict__ emb, int N, int D) {
    int row = blockIdx.x;
    const float* ei = emb + (size_t)row * D;
    int j1 = g_i1[row], j2 = g_i2[row];
    const float* e1 = emb + (size_t)j1 * D;
    const float* e2 = emb + (size_t)j2 * D;
    float d1 = 0.f, d2 = 0.f;
    for (int t = threadIdx.x; t < D; t += blockDim.x) {
        float v = ei[t];
        d1 = fmaf(v, e1[t], d1);
        d2 = fmaf(v, e2[t], d2);
    }
    #pragma unroll
    for (int o = 16; o > 0; o >>= 1) {
        d1 += __shfl_down_sync(0xffffffffu, d1, o);
        d2 += __shfl_down_sync(0xffffffffu, d2, o);
    }
    __shared__ float r1[4], r2[4];
    int w = threadIdx.x >> 5, l = threadIdx.x & 31;
    if (l == 0) { r1[w] = d1; r2[w] = d2; }
    __syncthreads();
    if (threadIdx.x == 0) {
        int nw = blockDim.x >> 5;
        float D1 = 0.f, D2s = 0.f;
        for (int i = 0; i < nw; i++) { D1 += r1[i]; D2s += r2[i]; }
        int labr = g_lab[row];
        float da = sqrtf(fmaxf(g_sq[row] + g_sq[j1] - 2.f * D1, 1e-12f));
        float db = sqrtf(fmaxf(g_sq[row] + g_sq[j2] - 2.f * D2s, 1e-12f));
        float va = (labr == g_lab[j1]) ? da : da - BIGF;
        float vb = (labr == g_lab[j2]) ? db : db - BIGF;
        float ea = fabsf(va - g_ap1[row]) / fmaxf(fabsf(va), 1.f);
        float eb = fabsf(vb - g_ap2[row]) / fmaxf(fabsf(vb), 1.f);
        if (ea > 1e-3f || eb > 1e-3f) g_bad = 1;
    }
}

// ---------------- fp32 fallback (proven R2 kernel), runs only if validation failed ----------------
#define BM 64
#define BN 64
#define BK 32
#define FTM 4
#define FTN 4
#define PAD 4

__global__ __launch_bounds__(256)
void fallback_dist_kernel(const float* __restrict__ emb, int N, int D) {
    if (*(volatile int*)&g_bad == 0) return;
    __shared__ float As[BK][BM + PAD];
    __shared__ float Bs[BK][BN + PAD];
    __shared__ float sqc[BN];
    __shared__ int   labc[BN];
    __shared__ float Sv1[BM][16], Sv2[BM][16], San[BM][16];
    __shared__ int   Si1[BM][16], Si2[BM][16];

    const int i0  = blockIdx.x * BM;
    const int jw  = N / NSPLIT;
    const int jlo = blockIdx.y * jw;
    const int jhi = jlo + jw;
    const int tid = threadIdx.x;
    const int tx  = tid & 15;
    const int ty  = tid >> 4;

    float v1[FTM], v2[FTM], an[FTM];
    int   i1[FTM], i2[FTM];
    int   labr[FTM];
    float sqr[FTM];
    #pragma unroll
    for (int m = 0; m < FTM; m++) {
        v1[m] = -FLT_MAX; v2[m] = -FLT_MAX; an[m] = FLT_MAX;
        i1[m] = 0; i2[m] = 0;
        int r = i0 + ty * FTM + m;
        labr[m] = g_lab[r];
        sqr[m]  = g_sq[r];
    }

    for (int j0 = jlo; j0 < jhi; j0 += BN) {
        if (tid < BN) { sqc[tid] = g_sq[j0 + tid]; labc[tid] = g_lab[j0 + tid]; }
        float acc[FTM][FTN];
        #pragma unroll
        for (int m = 0; m < FTM; m++)
            #pragma unroll
            for (int n = 0; n < FTN; n++) acc[m][n] = 0.f;

        for (int k0 = 0; k0 < D; k0 += BK) {
            __syncthreads();
            #pragma unroll
            for (int m = 0; m < 2; m++) {
                int idx4 = tid + m * 256;
                int r  = idx4 >> 3;
                int c4 = (idx4 & 7) << 2;
                float4 av = *reinterpret_cast<const float4*>(
                    &emb[(size_t)(i0 + r) * D + k0 + c4]);
                float4 bv = *reinterpret_cast<const float4*>(
                    &emb[(size_t)(j0 + r) * D + k0 + c4]);
                As[c4 + 0][r] = av.x; As[c4 + 1][r] = av.y;
                As[c4 + 2][r] = av.z; As[c4 + 3][r] = av.w;
                Bs[c4 + 0][r] = bv.x; Bs[c4 + 1][r] = bv.y;
                Bs[c4 + 2][r] = bv.z; Bs[c4 + 3][r] = bv.w;
            }
            __syncthreads();
            #pragma unroll
            for (int k = 0; k < BK; k++) {
                float4 af = *reinterpret_cast<const float4*>(&As[k][ty * FTM]);
                float4 bf = *reinterpret_cast<const float4*>(&Bs[k][tx * FTN]);
                float a[FTM] = {af.x, af.y, af.z, af.w};
                float b[FTN] = {bf.x, bf.y, bf.z, bf.w};
                #pragma unroll
                for (int m = 0; m < FTM; m++)
                    #pragma unroll
                    for (int n = 0; n < FTN; n++)
                        acc[m][n] = fmaf(a[m], b[n], acc[m][n]);
            }
        }

        #pragma unroll
        for (int m = 0; m < FTM; m++) {
            #pragma unroll
            for (int n = 0; n < FTN; n++) {
                int c  = tx * FTN + n;
                int jg = j0 + c;
                float d2 = sqr[m] + sqc[c] - 2.f * acc[m][n];
                d2 = fmaxf(d2, 1e-12f);
                float d = sqrtf(d2);
                bool same = (labr[m] == labc[c]);
                float v = same ? d : d - BIGF;
                float w = same ? d + BIGF : d;
                if (w < an[m]) an[m] = w;
                if (v > v1[m] || (v == v1[m] && jg < i1[m])) {
                    v2[m] = v1[m]; i2[m] = i1[m]; v1[m] = v; i1[m] = jg;
                } else if (v > v2[m] || (v == v2[m] && jg < i2[m])) {
                    v2[m] = v; i2[m] = jg;
                }
            }
        }
        __syncthreads();
    }

    #pragma unroll
    for (int m = 0; m < FTM; m++) {
        int r = ty * FTM + m;
        Sv1[r][tx] = v1[m]; Si1[r][tx] = i1[m];
        Sv2[r][tx] = v2[m]; Si2[r][tx] = i2[m];
        San[r][tx] = an[m];
    }
    __syncthreads();
    if (tid < BM) {
        int r = tid;
        float bv1 = -FLT_MAX, bv2 = -FLT_MAX, ban = FLT_MAX;
        int bi1 = 0, bi2 = 0;
        #pragma unroll 4
        for (int t = 0; t < 16; t++) {
            float a = San[r][t];
            if (a < ban) ban = a;
            float cv = Sv1[r][t]; int ci = Si1[r][t];
            if (cv > bv1 || (cv == bv1 && ci < bi1)) { bv2 = bv1; bi2 = bi1; bv1 = cv; bi1 = ci; }
            else if (cv > bv2 || (cv == bv2 && ci < bi2)) { bv2 = cv; bi2 = ci; }
            cv = Sv2[r][t]; ci = Si2[r][t];
            if (cv > bv1 || (cv == bv1 && ci < bi1)) { bv2 = bv1; bi2 = bi1; bv1 = cv; bi1 = ci; }
            else if (cv > bv2 || (cv == bv2 && ci < bi2)) { bv2 = cv; bi2 = ci; }
        }
        int ig = i0 + r;
        int s  = blockIdx.y;
        g_pv1[s * MAXN + ig] = bv1; g_pv2[s * MAXN + ig] = bv2;
        g_pi1[s * MAXN + ig] = bi1; g_pi2[s * MAXN + ig] = bi2;
        g_pan[s * MAXN + ig] = ban;
    }
}

// ---------------- alpha (2 dots per row) + per-row loss terms ----------------
__global__ void alpha_loss_kernel(const float* __restrict__ clot, int D2) {
    int row = blockIdx.x;
    const float* ci = clot + (size_t)row * D2;
    int j1 = g_i1[row], j2 = g_i2[row];
    const float* c1 = clot + (size_t)j1 * D2;
    const float* c2 = clot + (size_t)j2 * D2;
    float d1 = 0.f, d2 = 0.f;
    for (int t = threadIdx.x; t < D2; t += blockDim.x) {
        float v = ci[t];
        d1 = fmaf(v, c1[t], d1);
        d2 = fmaf(v, c2[t], d2);
    }
    #pragma unroll
    for (int o = 16; o > 0; o >>= 1) {
        d1 += __shfl_down_sync(0xffffffffu, d1, o);
        d2 += __shfl_down_sync(0xffffffffu, d2, o);
    }
    __shared__ float r1[4], r2[4];
    int w = threadIdx.x >> 5, l = threadIdx.x & 31;
    if (l == 0) { r1[w] = d1; r2[w] = d2; }
    __syncthreads();
    if (threadIdx.x == 0) {
        int nw = blockDim.x >> 5;
        float D1 = 0.f, D2s = 0.f;
        for (int i = 0; i < nw; i++) { D1 += r1[i]; D2s += r2[i]; }
        float a1 = D1  / (g_nrm[row] * g_nrm[j1]);
        float a2 = D2s / (g_nrm[row] * g_nrm[j2]);
        float dap1 = g_ap1[row], dap2 = g_ap2[row], dan = g_an[row];
        float y  = (a1 < a2) ? -1.f : 1.f;
        float ym = (a1 == a2) ? 0.f : 1.f;
        float x1 = dap2 * ym;
        float x2 = dap1 * ym + MARGINF * (a1 - a2 - y);
        float t11 = fmaxf(0.f, -y * (x1 - x2) + MARGINF);
        float ap1m = dap1 + MARGINF * (a1 - 1.f);
        float t13 = fmaxf(0.f, -(dan - ap1m) + MARGINF);
        g_l11[row] = t11;
        g_l13[row] = t13;
        g_pr[row]  = (dan > ap1m) ? 1.f : 0.f;
    }
}

// ---------------- deterministic final reduction ----------------
__global__ void final_kernel(float* __restrict__ out, int N) {
    __shared__ float s1[1024], s2[1024], s3[1024];
    int t = threadIdx.x;
    float a = 0.f, b = 0.f, c = 0.f;
    for (int i = t; i < N; i += 1024) { a += g_l11[i]; b += g_l13[i]; c += g_pr[i]; }
    s1[t] = a; s2[t] = b; s3[t] = c;
    __syncthreads();
    for (int o = 512; o > 0; o >>= 1) {
        if (t < o) { s1[t] += s1[t + o]; s2[t] += s2[t + o]; s3[t] += s3[t + o]; }
        __syncthreads();
    }
    if (t == 0) {
        float invN = 1.f / (float)N;
        out[0] = 0.1f * (s1[0] * invN) + (s2[0] * invN);  // loss
        out[1] = s3[0] * invN;                            // prec
    }
}

// ---------------- launch ----------------
extern "C" void kernel_launch(void* const* d_in, const int* in_sizes, int n_in,
                              void* d_out, int out_size) {
    const float* emb   = (const float*)d_in[0];
    const void*  label = d_in[1];
    const float* clot  = (const float*)d_in[2];
    float* out = (float*)d_out;

    const int N  = in_sizes[1];
    const int D  = in_sizes[0] / N;
    const int D2 = in_sizes[2] / N;

    detect_label_kernel<<<1, 32>>>((const int*)label);
    precompute_kernel<<<N, 256>>>(emb, clot, label, D, D2);
    convert_kernel<<<N, 128>>>(emb, N, D);
    dim3 grid(N / 128, NSPLIT);
    dist_hmma_kernel<<<grid, 512>>>(N, D);
    merge_split_kernel<<<(N + 255) / 256, 256>>>(N);
    validate_kernel<<<N, 128>>>(emb, N, D);
    dim3 fgrid(N / BM, NSPLIT);
    fallback_dist_kernel<<<fgrid, 256>>>(emb, N, D);
    merge_split_kernel<<<(N + 255) / 256, 256>>>(N);
    alpha_loss_kernel<<<N, 128>>>(clot, D2);
    final_kernel<<<1, 1024>>>(out, N);
}

// round 12
// speedup vs baseline: 1.7108x; 1.7108x over previous
#include <cuda_runtime.h>
#include <cuda_bf16.h>
#include <cfloat>
#include <cstdint>
#include <cstddef>

#define MARGINF 0.3f
#define BIGF    9999999.0f
#define MAXN    8192
#define NSPLIT  4
#define SKP     40        // padded smem row stride in elements (80B, conflict-free, 16B-mult)
#define NSTG    3
#define STG_TILE 10240    // bytes per 128xSKP bf16 tile
#define STG_BYTES (4 * STG_TILE)            // Ahi, Alo, Bhi, Blo
#define SMEM_TOT (NSTG * STG_BYTES + 1024)  // + sqc/labc

// ---------------- scratch (device globals; no allocation allowed) ----------------
__device__ __align__(16) __nv_bfloat16 g_hi[(size_t)MAXN * 1024];
__device__ __align__(16) __nv_bfloat16 g_lo[(size_t)MAXN * 1024];
__device__ float g_sq[MAXN];
__device__ float g_nrm[MAXN];
__device__ int   g_lab[MAXN];
__device__ float g_pv1[NSPLIT * MAXN];
__device__ float g_pv2[NSPLIT * MAXN];
__device__ int   g_pi1[NSPLIT * MAXN];
__device__ int   g_pi2[NSPLIT * MAXN];
__device__ float g_pan[NSPLIT * MAXN];
__device__ float g_ap1[MAXN];
__device__ float g_ap2[MAXN];
__device__ int   g_i1[MAXN];
__device__ int   g_i2[MAXN];
__device__ float g_an[MAXN];
__device__ float g_l11[MAXN];
__device__ float g_l13[MAXN];
__device__ float g_pr[MAXN];
__device__ int   g_lab64;
__device__ int   g_bad;

// ---------------- small asm helpers (all baseline sm_80+ features) ----------------
__device__ __forceinline__ uint32_t smem_u32(const void* p) {
    uint32_t a;
    asm("{ .reg .u64 t; cvta.to.shared.u64 t, %1; cvt.u32.u64 %0, t; }" : "=r"(a) : "l"(p));
    return a;
}
__device__ __forceinline__ void cp16(uint32_t s, const void* g) {
    asm volatile("cp.async.cg.shared.global [%0], [%1], 16;" :: "r"(s), "l"(g));
}
__device__ __forceinline__ void ldsm_x4(uint32_t& r0, uint32_t& r1, uint32_t& r2, uint32_t& r3, uint32_t a) {
    asm volatile("ldmatrix.sync.aligned.m8n8.x4.shared.b16 {%0,%1,%2,%3}, [%4];"
        : "=r"(r0), "=r"(r1), "=r"(r2), "=r"(r3) : "r"(a));
}
__device__ __forceinline__ void ldsm_x2(uint32_t& r0, uint32_t& r1, uint32_t a) {
    asm volatile("ldmatrix.sync.aligned.m8n8.x2.shared.b16 {%0,%1}, [%2];"
        : "=r"(r0), "=r"(r1) : "r"(a));
}
__device__ __forceinline__ void mma16816(float* c, const uint32_t* a,
                                         uint32_t b0, uint32_t b1) {
    asm volatile(
        "mma.sync.aligned.m16n8k16.row.col.f32.bf16.bf16.f32 "
        "{%0,%1,%2,%3}, {%4,%5,%6,%7}, {%8,%9}, {%0,%1,%2,%3};"
        : "+f"(c[0]), "+f"(c[1]), "+f"(c[2]), "+f"(c[3])
        : "r"(a[0]), "r"(a[1]), "r"(a[2]), "r"(a[3]), "r"(b0), "r"(b1));
}

// ---------------- label dtype detection + flag reset ----------------
__global__ void detect_label_kernel(const int* lab_raw) {
    if (threadIdx.x == 0 && blockIdx.x == 0) {
        int nz = 0;
        for (int i = 0; i < 64; i++) nz |= lab_raw[2 * i + 1];
        g_lab64 = (nz == 0) ? 1 : 0;
        g_bad = 0;
    }
}

// ---------------- per-row precompute: sq, nrm, label32 ----------------
__global__ void precompute_kernel(const float* __restrict__ emb,
                                  const float* __restrict__ clot,
                                  const void* __restrict__ label,
                                  int D, int D2) {
    int row = blockIdx.x;
    const float* e = emb + (size_t)row * D;
    const float* c = clot + (size_t)row * D2;
    float s = 0.f, s2 = 0.f;
    for (int t = threadIdx.x; t < D; t += blockDim.x) { float v = e[t]; s += v * v; }
    for (int t = threadIdx.x; t < D2; t += blockDim.x) { float v = c[t]; s2 += v * v; }
    #pragma unroll
    for (int o = 16; o > 0; o >>= 1) {
        s  += __shfl_down_sync(0xffffffffu, s,  o);
        s2 += __shfl_down_sync(0xffffffffu, s2, o);
    }
    __shared__ float red[2][8];
    int w = threadIdx.x >> 5, l = threadIdx.x & 31;
    if (l == 0) { red[0][w] = s; red[1][w] = s2; }
    __syncthreads();
    if (threadIdx.x == 0) {
        float a = 0.f, b = 0.f;
        int nw = blockDim.x >> 5;
        for (int i = 0; i < nw; i++) { a += red[0][i]; b += red[1][i]; }
        g_sq[row]  = a;
        g_nrm[row] = sqrtf(b);
        if (g_lab64) g_lab[row] = (int)((const long long*)label)[row];
        else         g_lab[row] = ((const int*)label)[row];
    }
}

// ---------------- convert fp32 -> bf16 hi/lo (row-major) ----------------
__global__ void convert_kernel(const float* __restrict__ emb, int N, int D) {
    int row = blockIdx.x;
    for (int k8 = threadIdx.x * 8; k8 < D; k8 += blockDim.x * 8) {
        float4 x0 = *reinterpret_cast<const float4*>(emb + (size_t)row * D + k8);
        float4 x1 = *reinterpret_cast<const float4*>(emb + (size_t)row * D + k8 + 4);
        float xs[8] = {x0.x, x0.y, x0.z, x0.w, x1.x, x1.y, x1.z, x1.w};
        unsigned short hs[8], ls[8];
        #pragma unroll
        for (int e = 0; e < 8; e++) {
            __nv_bfloat16 h = __float2bfloat16(xs[e]);
            float r = xs[e] - __bfloat162float(h);
            __nv_bfloat16 l = __float2bfloat16(r);
            hs[e] = __bfloat16_as_ushort(h);
            ls[e] = __bfloat16_as_ushort(l);
        }
        uint4 hp, lp;
        hp.x = ((uint32_t)hs[1] << 16) | hs[0]; hp.y = ((uint32_t)hs[3] << 16) | hs[2];
        hp.z = ((uint32_t)hs[5] << 16) | hs[4]; hp.w = ((uint32_t)hs[7] << 16) | hs[6];
        lp.x = ((uint32_t)ls[1] << 16) | ls[0]; lp.y = ((uint32_t)ls[3] << 16) | ls[2];
        lp.z = ((uint32_t)ls[5] << 16) | ls[4]; lp.w = ((uint32_t)ls[7] << 16) | ls[6];
        *reinterpret_cast<uint4*>(g_hi + (size_t)row * D + k8) = hp;
        *reinterpret_cast<uint4*>(g_lo + (size_t)row * D + k8) = lp;
    }
}

// ---------------- fused bf16 mma.sync GEMM (fused 3-product stages) + row reductions ----------
// BM=BN=128, BK=32 per stage; each stage holds Ahi/Alo/Bhi/Blo and issues 3 products.
// 512 threads = 16 warps in 4(m) x 4(n) grid; each warp 2x4 m16n8k16 tiles.
__global__ __launch_bounds__(512, 1)
void dist_hmma_kernel(int N, int D) {
    extern __shared__ __align__(16) char smraw[];
    uint32_t sb = smem_u32(smraw);
    float* sqc  = (float*)(smraw + NSTG * STG_BYTES);
    int*   labc = (int*)(smraw + NSTG * STG_BYTES + 512);

    const int tid  = threadIdx.x;
    const int lane = tid & 31;
    const int wid  = tid >> 5;
    const int wm   = wid >> 2;        // 0..3
    const int wn   = wid & 3;         // 0..3
    const int g    = lane >> 2;       // 0..7
    const int q    = lane & 3;        // 0..3
    const int i0   = blockIdx.x * 128;
    const int jw   = N / NSPLIT;
    const int jlo  = blockIdx.y * jw;
    const int nk   = D / 32;          // stages per j-tile (fused 3 products each)

    // ldmatrix lane-address components
    const int ar = (lane & 7) + ((lane >> 3) & 1) * 8;  // A: row within m16
    const int ak = (lane >> 4) * 8;                     // A: k-offset
    const int bl = lane & 7;                            // B: row within n8
    const int bk = ((lane >> 3) & 1) * 8;               // B: k-offset

    // per-thread row constants (4 rows owned: 2 mi-tiles x {g, g+8})
    float sqr4[4]; int labr4[4];
    #pragma unroll
    for (int mi = 0; mi < 2; mi++)
        #pragma unroll
        for (int rr = 0; rr < 2; rr++) {
            int r = i0 + wm * 32 + mi * 16 + rr * 8 + g;
            sqr4[mi * 2 + rr]  = g_sq[r];
            labr4[mi * 2 + rr] = g_lab[r];
        }

    float v1[4], v2[4], an[4]; int ix1[4], ix2[4];
    #pragma unroll
    for (int s = 0; s < 4; s++) {
        v1[s] = -FLT_MAX; v2[s] = -FLT_MAX; an[s] = FLT_MAX; ix1[s] = 0; ix2[s] = 0;
    }

    const int crow = tid >> 2, cchk = tid & 3;   // cp.async mapping: 128 rows x 4 16B chunks
    const uint32_t coff = (uint32_t)(crow * SKP + cchk * 8) * 2;

    for (int jt = 0; jt < jw / 128; jt++) {
        const int j0 = jlo + jt * 128;
        __syncthreads();   // prior j-tile fully consumed (compute + sqc reads)
        if (tid < 128) { sqc[tid] = g_sq[j0 + tid]; labc[tid] = g_lab[j0 + tid]; }

        float acc[2][4][4];
        #pragma unroll
        for (int mi = 0; mi < 2; mi++)
            #pragma unroll
            for (int ni = 0; ni < 4; ni++)
                #pragma unroll
                for (int e = 0; e < 4; e++) acc[mi][ni][e] = 0.f;

        // prologue: prefetch stages 0,1
        #pragma unroll
        for (int ps = 0; ps < 2; ps++) {
            uint32_t dst = sb + (uint32_t)ps * STG_BYTES + coff;
            const __nv_bfloat16* ga = (size_t)(i0 + crow) * D + ps * 32 + cchk * 8 + g_hi;
            const __nv_bfloat16* gb = (size_t)(j0 + crow) * D + ps * 32 + cchk * 8 + g_hi;
            const __nv_bfloat16* la = ga + (g_lo - g_hi);
            const __nv_bfloat16* lb = gb + (g_lo - g_hi);
            cp16(dst, ga);
            cp16(dst + STG_TILE, la);
            cp16(dst + 2 * STG_TILE, gb);
            cp16(dst + 3 * STG_TILE, lb);
            asm volatile("cp.async.commit_group;");
        }

        for (int s = 0; s < nk; s++) {
            if (s + 1 < nk) asm volatile("cp.async.wait_group 1;");
            else            asm volatile("cp.async.wait_group 0;");
            __syncthreads();   // stage s visible; all warps past compute(s-1)

            if (s + 2 < nk) {
                int ps = s + 2;
                uint32_t dst = sb + (uint32_t)(ps % NSTG) * STG_BYTES + coff;
                const __nv_bfloat16* ga = g_hi + (size_t)(i0 + crow) * D + ps * 32 + cchk * 8;
                const __nv_bfloat16* gb = g_hi + (size_t)(j0 + crow) * D + ps * 32 + cchk * 8;
                cp16(dst, ga);
                cp16(dst + STG_TILE, ga + (g_lo - g_hi));
                cp16(dst + 2 * STG_TILE, gb);
                cp16(dst + 3 * STG_TILE, gb + (g_lo - g_hi));
                asm volatile("cp.async.commit_group;");
            }

            // compute stage s: acc += Ahi*Bhi + Ahi*Blo + Alo*Bhi
            uint32_t bAh = sb + (uint32_t)(s % NSTG) * STG_BYTES;
            uint32_t bAl = bAh + STG_TILE;
            uint32_t bBh = bAh + 2 * STG_TILE;
            uint32_t bBl = bAh + 3 * STG_TILE;
            #pragma unroll
            for (int kk = 0; kk < 32; kk += 16) {
                uint32_t ah[2][4], al[2][4], bh[4][2], blo[4][2];
                #pragma unroll
                for (int ni = 0; ni < 4; ni++) {
                    uint32_t bo = (uint32_t)(((wn * 32 + ni * 8 + bl) * SKP) + kk + bk) * 2;
                    ldsm_x2(bh[ni][0],  bh[ni][1],  bBh + bo);
                    ldsm_x2(blo[ni][0], blo[ni][1], bBl + bo);
                }
                #pragma unroll
                for (int mi = 0; mi < 2; mi++) {
                    uint32_t ao = (uint32_t)(((wm * 32 + mi * 16 + ar) * SKP) + kk + ak) * 2;
                    ldsm_x4(ah[mi][0], ah[mi][1], ah[mi][2], ah[mi][3], bAh + ao);
                    ldsm_x4(al[mi][0], al[mi][1], al[mi][2], al[mi][3], bAl + ao);
                }
                #pragma unroll
                for (int mi = 0; mi < 2; mi++)
                    #pragma unroll
                    for (int ni = 0; ni < 4; ni++) {
                        mma16816(acc[mi][ni], ah[mi], bh[ni][0],  bh[ni][1]);
                        mma16816(acc[mi][ni], ah[mi], blo[ni][0], blo[ni][1]);
                        mma16816(acc[mi][ni], al[mi], bh[ni][0],  bh[ni][1]);
                    }
            }
        }

        // ---- tile epilogue: masked top2/min updates in d^2 domain ----
        #pragma unroll
        for (int mi = 0; mi < 2; mi++)
            #pragma unroll
            for (int rr = 0; rr < 2; rr++) {
                int st = mi * 2 + rr;
                #pragma unroll
                for (int ni = 0; ni < 4; ni++)
                    #pragma unroll
                    for (int e = 0; e < 2; e++) {
                        int col = wn * 32 + ni * 8 + q * 2 + e;
                        float dot = acc[mi][ni][rr * 2 + e];
                        float d2v = fmaf(-2.f, dot, sqr4[st] + sqc[col]);
                        d2v = fmaxf(d2v, 1e-12f);
                        bool same = (labr4[st] == labc[col]);
                        float v = same ? d2v : d2v - BIGF;
                        float w = same ? d2v + BIGF : d2v;
                        if (w < an[st]) an[st] = w;
                        int jg = j0 + col;
                        if (v > v1[st])      { v2[st] = v1[st]; ix2[st] = ix1[st]; v1[st] = v; ix1[st] = jg; }
                        else if (v > v2[st]) { v2[st] = v; ix2[st] = jg; }
                    }
            }
    }

    // ---- cross-thread merge: 16 partials per row via smem (alias tile memory) ----
    __syncthreads();
    float* Sv1 = (float*)smraw;               // [128][16]
    float* Sv2 = (float*)(smraw + 8192);
    float* San = (float*)(smraw + 16384);
    int*   Si1 = (int*)(smraw + 24576);
    int*   Si2 = (int*)(smraw + 32768);
    int slot = wn * 4 + q;
    #pragma unroll
    for (int mi = 0; mi < 2; mi++)
        #pragma unroll
        for (int rr = 0; rr < 2; rr++) {
            int st = mi * 2 + rr;
            int rowL = wm * 32 + mi * 16 + rr * 8 + g;
            Sv1[rowL * 16 + slot] = v1[st]; Si1[rowL * 16 + slot] = ix1[st];
            Sv2[rowL * 16 + slot] = v2[st]; Si2[rowL * 16 + slot] = ix2[st];
            San[rowL * 16 + slot] = an[st];
        }
    __syncthreads();
    if (tid < 128) {
        int r = tid;
        float bv1 = -FLT_MAX, bv2 = -FLT_MAX, ban = FLT_MAX;
        int bi1 = 0, bi2 = 0;
        #pragma unroll 4
        for (int t = 0; t < 16; t++) {
            float a = San[r * 16 + t];
            if (a < ban) ban = a;
            float cv = Sv1[r * 16 + t]; int ci = Si1[r * 16 + t];
            if (cv > bv1 || (cv == bv1 && ci < bi1)) { bv2 = bv1; bi2 = bi1; bv1 = cv; bi1 = ci; }
            else if (cv > bv2 || (cv == bv2 && ci < bi2)) { bv2 = cv; bi2 = ci; }
            cv = Sv2[r * 16 + t]; ci = Si2[r * 16 + t];
            if (cv > bv1 || (cv == bv1 && ci < bi1)) { bv2 = bv1; bi2 = bi1; bv1 = cv; bi1 = ci; }
            else if (cv > bv2 || (cv == bv2 && ci < bi2)) { bv2 = cv; bi2 = ci; }
        }
        // d^2 -> d domain (undo BIG masking, sqrt, re-apply)
        float ap1 = (bv1 > -BIGF * 0.5f) ? sqrtf(bv1) : (sqrtf(fmaxf(bv1 + BIGF, 1e-12f)) - BIGF);
        float ap2 = (bv2 > -BIGF * 0.5f) ? sqrtf(bv2) : (sqrtf(fmaxf(bv2 + BIGF, 1e-12f)) - BIGF);
        float anv = (ban <  BIGF * 0.5f) ? sqrtf(ban) : (sqrtf(fmaxf(ban - BIGF, 1e-12f)) + BIGF);
        int ig = i0 + r;
        int sidx = blockIdx.y;
        g_pv1[sidx * MAXN + ig] = ap1; g_pv2[sidx * MAXN + ig] = ap2;
        g_pi1[sidx * MAXN + ig] = bi1; g_pi2[sidx * MAXN + ig] = bi2;
        g_pan[sidx * MAXN + ig] = anv;
    }
}

// ---------------- merge column splits (deterministic) ----------------
__global__ void merge_split_kernel(int N) {
    int r = blockIdx.x * blockDim.x + threadIdx.x;
    if (r >= N) return;
    float bv1 = -FLT_MAX, bv2 = -FLT_MAX, ban = FLT_MAX;
    int bi1 = 0, bi2 = 0;
    #pragma unroll
    for (int s = 0; s < NSPLIT; s++) {
        float a = g_pan[s * MAXN + r];
        if (a < ban) ban = a;
        float cv = g_pv1[s * MAXN + r]; int ci = g_pi1[s * MAXN + r];
        if (cv > bv1 || (cv == bv1 && ci < bi1)) { bv2 = bv1; bi2 = bi1; bv1 = cv; bi1 = ci; }
        else if (cv > bv2 || (cv == bv2 && ci < bi2)) { bv2 = cv; bi2 = ci; }
        cv = g_pv2[s * MAXN + r]; ci = g_pi2[s * MAXN + r];
        if (cv > bv1 || (cv == bv1 && ci < bi1)) { bv2 = bv1; bi2 = bi1; bv1 = cv; bi1 = ci; }
        else if (cv > bv2 || (cv == bv2 && ci < bi2)) { bv2 = cv; bi2 = ci; }
    }
    g_ap1[r] = bv1; g_ap2[r] = bv2;
    g_i1[r] = bi1;  g_i2[r] = bi2;
    g_an[r] = ban;
}

// ---------------- validate vs exact fp32 at selected indices ----------------
__global__ void validate_kernel(const float* __restrict__ emb, int N, int D) {
    int row = blockIdx.x;
    const float* ei = emb + (size_t)row * D;
    int j1 = g_i1[row], j2 = g_i2[row];
    const float* e1 = emb + (size_t)j1 * D;
    const float* e2 = emb + (size_t)j2 * D;
    float d1 = 0.f, d2 = 0.f;
    for (int t = threadIdx.x; t < D; t += blockDim.x) {
        float v = ei[t];
        d1 = fmaf(v, e1[t], d1);
        d2 = fmaf(v, e2[t], d2);
    }
    #pragma unroll
    for (int o = 16; o > 0; o >>= 1) {
        d1 += __shfl_down_sync(0xffffffffu, d1, o);
        d2 += __shfl_down_sync(0xffffffffu, d2, o);
    }
    __shared__ float r1[4], r2[4];
    int w = threadIdx.x >> 5, l = threadIdx.x & 31;
    if (l == 0) { r1[w] = d1; r2[w] = d2; }
    __syncthreads();
    if (threadIdx.x == 0) {
        int nw = blockDim.x >> 5;
        float D1 = 0.f, D2s = 0.f;
        for (int i = 0; i < nw; i++) { D1 += r1[i]; D2s += r2[i]; }
        int labr = g_lab[row];
        float da = sqrtf(fmaxf(g_sq[row] + g_sq[j1] - 2.f * D1, 1e-12f));
        float db = sqrtf(fmaxf(g_sq[row] + g_sq[j2] - 2.f * D2s, 1e-12f));
        float va = (labr == g_lab[j1]) ? da : da - BIGF;
        float vb = (labr == g_lab[j2]) ? db : db - BIGF;
        float ea = fabsf(va - g_ap1[row]) / fmaxf(fabsf(va), 1.f);
        float eb = fabsf(vb - g_ap2[row]) / fmaxf(fabsf(vb), 1.f);
        if (ea > 1e-3f || eb > 1e-3f) g_bad = 1;
    }
}

// ---------------- fp32 fallback (proven R2 kernel), runs only if validation failed ----------------
#define BM 64
#define BN 64
#define BK 32
#define FTM 4
#define FTN 4
#define PAD 4

__global__ __launch_bounds__(256)
void fallback_dist_kernel(const float* __restrict__ emb, int N, int D) {
    if (*(volatile int*)&g_bad == 0) return;
    __shared__ float As[BK][BM + PAD];
    __shared__ float Bs[BK][BN + PAD];
    __shared__ float sqc[BN];
    __shared__ int   labc[BN];
    __shared__ float Sv1[BM][16], Sv2[BM][16], San[BM][16];
    __shared__ int   Si1[BM][16], Si2[BM][16];

    const int i0  = blockIdx.x * BM;
    const int jw  = N / NSPLIT;
    const int jlo = blockIdx.y * jw;
    const int jhi = jlo + jw;
    const int tid = threadIdx.x;
    const int tx  = tid & 15;
    const int ty  = tid >> 4;

    float v1[FTM], v2[FTM], an[FTM];
    int   i1[FTM], i2[FTM];
    int   labr[FTM];
    float sqr[FTM];
    #pragma unroll
    for (int m = 0; m < FTM; m++) {
        v1[m] = -FLT_MAX; v2[m] = -FLT_MAX; an[m] = FLT_MAX;
        i1[m] = 0; i2[m] = 0;
        int r = i0 + ty * FTM + m;
        labr[m] = g_lab[r];
        sqr[m]  = g_sq[r];
    }

    for (int j0 = jlo; j0 < jhi; j0 += BN) {
        if (tid < BN) { sqc[tid] = g_sq[j0 + tid]; labc[tid] = g_lab[j0 + tid]; }
        float acc[FTM][FTN];
        #pragma unroll
        for (int m = 0; m < FTM; m++)
            #pragma unroll
            for (int n = 0; n < FTN; n++) acc[m][n] = 0.f;

        for (int k0 = 0; k0 < D; k0 += BK) {
            __syncthreads();
            #pragma unroll
            for (int m = 0; m < 2; m++) {
                int idx4 = tid + m * 256;
                int r  = idx4 >> 3;
                int c4 = (idx4 & 7) << 2;
                float4 av = *reinterpret_cast<const float4*>(
                    &emb[(size_t)(i0 + r) * D + k0 + c4]);
                float4 bv = *reinterpret_cast<const float4*>(
                    &emb[(size_t)(j0 + r) * D + k0 + c4]);
                As[c4 + 0][r] = av.x; As[c4 + 1][r] = av.y;
                As[c4 + 2][r] = av.z; As[c4 + 3][r] = av.w;
                Bs[c4 + 0][r] = bv.x; Bs[c4 + 1][r] = bv.y;
                Bs[c4 + 2][r] = bv.z; Bs[c4 + 3][r] = bv.w;
            }
            __syncthreads();
            #pragma unroll
            for (int k = 0; k < BK; k++) {
                float4 af = *reinterpret_cast<const float4*>(&As[k][ty * FTM]);
                float4 bf = *reinterpret_cast<const float4*>(&Bs[k][tx * FTN]);
                float a[FTM] = {af.x, af.y, af.z, af.w};
                float b[FTN] = {bf.x, bf.y, bf.z, bf.w};
                #pragma unroll
                for (int m = 0; m < FTM; m++)
                    #pragma unroll
                    for (int n = 0; n < FTN; n++)
                        acc[m][n] = fmaf(a[m], b[n], acc[m][n]);
            }
        }

        #pragma unroll
        for (int m = 0; m < FTM; m++) {
            #pragma unroll
            for (int n = 0; n < FTN; n++) {
                int c  = tx * FTN + n;
                int jg = j0 + c;
                float d2 = sqr[m] + sqc[c] - 2.f * acc[m][n];
                d2 = fmaxf(d2, 1e-12f);
                float d = sqrtf(d2);
                bool same = (labr[m] == labc[c]);
                float v = same ? d : d - BIGF;
                float w = same ? d + BIGF : d;
                if (w < an[m]) an[m] = w;
                if (v > v1[m] || (v == v1[m] && jg < i1[m])) {
                    v2[m] = v1[m]; i2[m] = i1[m]; v1[m] = v; i1[m] = jg;
                } else if (v > v2[m] || (v == v2[m] && jg < i2[m])) {
                    v2[m] = v; i2[m] = jg;
                }
            }
        }
        __syncthreads();
    }

    #pragma unroll
    for (int m = 0; m < FTM; m++) {
        int r = ty * FTM + m;
        Sv1[r][tx] = v1[m]; Si1[r][tx] = i1[m];
        Sv2[r][tx] = v2[m]; Si2[r][tx] = i2[m];
        San[r][tx] = an[m];
    }
    __syncthreads();
    if (tid < BM) {
        int r = tid;
        float bv1 = -FLT_MAX, bv2 = -FLT_MAX, ban = FLT_MAX;
        int bi1 = 0, bi2 = 0;
        #pragma unroll 4
        for (int t = 0; t < 16; t++) {
            float a = San[r][t];
            if (a < ban) ban = a;
            float cv = Sv1[r][t]; int ci = Si1[r][t];
            if (cv > bv1 || (cv == bv1 && ci < bi1)) { bv2 = bv1; bi2 = bi1; bv1 = cv; bi1 = ci; }
            else if (cv > bv2 || (cv == bv2 && ci < bi2)) { bv2 = cv; bi2 = ci; }
            cv = Sv2[r][t]; ci = Si2[r][t];
            if (cv > bv1 || (cv == bv1 && ci < bi1)) { bv2 = bv1; bi2 = bi1; bv1 = cv; bi1 = ci; }
            else if (cv > bv2 || (cv == bv2 && ci < bi2)) { bv2 = cv; bi2 = ci; }
        }
        int ig = i0 + r;
        int s  = blockIdx.y;
        g_pv1[s * MAXN + ig] = bv1; g_pv2[s * MAXN + ig] = bv2;
        g_pi1[s * MAXN + ig] = bi1; g_pi2[s * MAXN + ig] = bi2;
        g_pan[s * MAXN + ig] = ban;
    }
}

// ---------------- alpha (2 dots per row) + per-row loss terms ----------------
__global__ void alpha_loss_kernel(const float* __restrict__ clot, int D2) {
    int row = blockIdx.x;
    const float* ci = clot + (size_t)row * D2;
    int j1 = g_i1[row], j2 = g_i2[row];
    const float* c1 = clot + (size_t)j1 * D2;
    const float* c2 = clot + (size_t)j2 * D2;
    float d1 = 0.f, d2 = 0.f;
    for (int t = threadIdx.x; t < D2; t += blockDim.x) {
        float v = ci[t];
        d1 = fmaf(v, c1[t], d1);
        d2 = fmaf(v, c2[t], d2);
    }
    #pragma unroll
    for (int o = 16; o > 0; o >>= 1) {
        d1 += __shfl_down_sync(0xffffffffu, d1, o);
        d2 += __shfl_down_sync(0xffffffffu, d2, o);
    }
    __shared__ float r1[4], r2[4];
    int w = threadIdx.x >> 5, l = threadIdx.x & 31;
    if (l == 0) { r1[w] = d1; r2[w] = d2; }
    __syncthreads();
    if (threadIdx.x == 0) {
        int nw = blockDim.x >> 5;
        float D1 = 0.f, D2s = 0.f;
        for (int i = 0; i < nw; i++) { D1 += r1[i]; D2s += r2[i]; }
        float a1 = D1  / (g_nrm[row] * g_nrm[j1]);
        float a2 = D2s / (g_nrm[row] * g_nrm[j2]);
        float dap1 = g_ap1[row], dap2 = g_ap2[row], dan = g_an[row];
        float y  = (a1 < a2) ? -1.f : 1.f;
        float ym = (a1 == a2) ? 0.f : 1.f;
        float x1 = dap2 * ym;
        float x2 = dap1 * ym + MARGINF * (a1 - a2 - y);
        float t11 = fmaxf(0.f, -y * (x1 - x2) + MARGINF);
        float ap1m = dap1 + MARGINF * (a1 - 1.f);
        float t13 = fmaxf(0.f, -(dan - ap1m) + MARGINF);
        g_l11[row] = t11;
        g_l13[row] = t13;
        g_pr[row]  = (dan > ap1m) ? 1.f : 0.f;
    }
}

// ---------------- deterministic final reduction ----------------
__global__ void final_kernel(float* __restrict__ out, int N) {
    __shared__ float s1[1024], s2[1024], s3[1024];
    int t = threadIdx.x;
    float a = 0.f, b = 0.f, c = 0.f;
    for (int i = t; i < N; i += 1024) { a += g_l11[i]; b += g_l13[i]; c += g_pr[i]; }
    s1[t] = a; s2[t] = b; s3[t] = c;
    __syncthreads();
    for (int o = 512; o > 0; o >>= 1) {
        if (t < o) { s1[t] += s1[t + o]; s2[t] += s2[t + o]; s3[t] += s3[t + o]; }
        __syncthreads();
    }
    if (t == 0) {
        float invN = 1.f / (float)N;
        out[0] = 0.1f * (s1[0] * invN) + (s2[0] * invN);  // loss
        out[1] = s3[0] * invN;                            // prec
    }
}

// ---------------- launch ----------------
extern "C" void kernel_launch(void* const* d_in, const int* in_sizes, int n_in,
                              void* d_out, int out_size) {
    const float* emb   = (const float*)d_in[0];
    const void*  label = d_in[1];
    const float* clot  = (const float*)d_in[2];
    float* out = (float*)d_out;

    const int N  = in_sizes[1];
    const int D  = in_sizes[0] / N;
    const int D2 = in_sizes[2] / N;

    cudaFuncSetAttribute(dist_hmma_kernel, cudaFuncAttributeMaxDynamicSharedMemorySize, SMEM_TOT);

    detect_label_kernel<<<1, 32>>>((const int*)label);
    precompute_kernel<<<N, 256>>>(emb, clot, label, D, D2);
    convert_kernel<<<N, 128>>>(emb, N, D);
    dim3 grid(N / 128, NSPLIT);
    dist_hmma_kernel<<<grid, 512, SMEM_TOT>>>(N, D);
    merge_split_kernel<<<(N + 255) / 256, 256>>>(N);
    validate_kernel<<<N, 128>>>(emb, N, D);
    dim3 fgrid(N / BM, NSPLIT);
    fallback_dist_kernel<<<fgrid, 256>>>(emb, N, D);
    merge_split_kernel<<<(N + 255) / 256, 256>>>(N);
    alpha_loss_kernel<<<N, 128>>>(clot, D2);
    final_kernel<<<1, 1024>>>(out, N);
}